// round 16
// baseline (speedup 1.0000x reference)
#include <cuda_runtime.h>
#include <cuda_fp16.h>
#include <math.h>
#include <stdint.h>

// Problem constants: N=20000, E=640000, S=128, V=16, E_DIM=32
#define MAXN 20000

__device__ float g_agg_s[MAXN * 128];
__device__ float g_agg_v[MAXN * 48];

__device__ float g_Y1[MAXN * 128];
__device__ float g_Y2[MAXN * 128];
__device__ float g_Z[MAXN * 128];
__device__ float g_vn[MAXN * 16];
__device__ float g_VA[MAXN * 48];
__device__ float g_VB[MAXN * 48];
__device__ float g_UVA[MAXN * 48];

__device__ __half g_W1ahi[128 * 128];
__device__ __half g_W1alo[128 * 128];
__device__ __half g_W1bhi[128 * 128];
__device__ __half g_W1blo[128 * 128];
__device__ __half g_W1phi[80 * 128];
__device__ __half g_W1plo[80 * 128];
__device__ __half g_W2hi[128 * 128];
__device__ __half g_W2lo[128 * 128];
__device__ __half g_Wgphi[128 * 16];
__device__ __half g_Wgplo[128 * 16];
__device__ float  g_bgp[16];
__device__ __half g_U1ahi[128 * 128];
__device__ __half g_U1alo[128 * 128];
// upd-GVP mma weights
__device__ __half g_U1bhi[160 * 128];   // uW1 rows 128..287
__device__ __half g_U1blo[160 * 128];
__device__ __half g_U2hi[128 * 128];
__device__ __half g_U2lo[128 * 128];
__device__ __half g_UWgphi[128 * 16];   // uW2 @ uWg
__device__ __half g_UWgplo[128 * 16];
__device__ float  g_ubgp[16];           // ub2 @ uWg + ubg

__device__ __forceinline__ float sigmoidf_(float x) {
    return 1.0f / (1.0f + __expf(-x));
}
__device__ __forceinline__ uint32_t smem_to_u32(const void* p) {
    uint32_t a;
    asm("{ .reg .u64 t; cvta.to.shared.u64 t, %1; cvt.u32.u64 %0, t; }"
        : "=r"(a) : "l"(p));
    return a;
}
__device__ __forceinline__ void ldsm4(uint32_t addr, uint32_t* r) {
    asm volatile("ldmatrix.sync.aligned.m8n8.x4.shared.b16 {%0,%1,%2,%3}, [%4];"
        : "=r"(r[0]), "=r"(r[1]), "=r"(r[2]), "=r"(r[3]) : "r"(addr));
}
__device__ __forceinline__ void ldsm4t(uint32_t addr, uint32_t* r) {
    asm volatile("ldmatrix.sync.aligned.m8n8.x4.trans.shared.b16 {%0,%1,%2,%3}, [%4];"
        : "=r"(r[0]), "=r"(r[1]), "=r"(r[2]), "=r"(r[3]) : "r"(addr));
}
__device__ __forceinline__ void mma_f16(float* c, const uint32_t* a, const uint32_t* b) {
    asm volatile(
        "mma.sync.aligned.m16n8k16.row.col.f32.f16.f16.f32 "
        "{%0,%1,%2,%3}, {%4,%5,%6,%7}, {%8,%9}, {%0,%1,%2,%3};"
        : "+f"(c[0]), "+f"(c[1]), "+f"(c[2]), "+f"(c[3])
        : "r"(a[0]), "r"(a[1]), "r"(a[2]), "r"(a[3]), "r"(b[0]), "r"(b[1]));
}
__device__ __forceinline__ uint32_t pack_h2(float x0, float x1) {
    __half2 t = __floats2half2_rn(x0, x1);
    return *(uint32_t*)&t;
}
__device__ __forceinline__ void red4(float* p, float a, float b, float c, float d) {
    asm volatile("red.global.add.v4.f32 [%0], {%1, %2, %3, %4};"
        :: "l"(p), "f"(a), "f"(b), "f"(c), "f"(d) : "memory");
}
__device__ __forceinline__ void red2(float* p, float a, float b) {
    asm volatile("red.global.add.v2.f32 [%0], {%1, %2};"
        :: "l"(p), "f"(a), "f"(b) : "memory");
}
__device__ __forceinline__ void cp_async16(uint32_t saddr, const void* gptr) {
    asm volatile(
        "{ .reg .u64 g; cvta.to.global.u64 g, %1; "
        "cp.async.cg.shared.global [%0], [g], 16; }"
        :: "r"(saddr), "l"(gptr) : "memory");
}
#define CP_COMMIT() asm volatile("cp.async.commit_group;" ::: "memory")
#define CP_WAIT0()  asm volatile("cp.async.wait_group 0;" ::: "memory")

// ---------------------------------------------------------------------------
__global__ void prep_weights(const float* __restrict__ W1,
                             const float* __restrict__ W2,
                             const float* __restrict__ b2,
                             const float* __restrict__ Wg,
                             const float* __restrict__ bg,
                             const float* __restrict__ uW1,
                             const float* __restrict__ uW2,
                             const float* __restrict__ ub2,
                             const float* __restrict__ uWg,
                             const float* __restrict__ ubg) {
    int i = blockIdx.x * blockDim.x + threadIdx.x;
    if (i < 80 * 128) {
        int k = i >> 7;
        float val = (k < 66) ? W1[(256 + k) * 128 + (i & 127)] : 0.0f;
        __half h = __float2half_rn(val);
        g_W1phi[i] = h;
        g_W1plo[i] = __float2half_rn(val - __half2float(h));
    } else if (i < 26624) {
        int j = i - 10240;
        float val = W1[j];
        __half h = __float2half_rn(val);
        g_W1ahi[j] = h;
        g_W1alo[j] = __float2half_rn(val - __half2float(h));
    } else if (i < 43008) {
        int j = i - 26624;
        float val = W1[128 * 128 + j];
        __half h = __float2half_rn(val);
        g_W1bhi[j] = h;
        g_W1blo[j] = __float2half_rn(val - __half2float(h));
    } else if (i < 59392) {
        int j = i - 43008;
        float val = W2[j];
        __half h = __float2half_rn(val);
        g_W2hi[j] = h;
        g_W2lo[j] = __float2half_rn(val - __half2float(h));
    } else if (i < 61440) {
        int j = i - 59392;
        int k = j >> 4, w = j & 15;
        float a = 0.0f;
        for (int c = 0; c < 128; ++c)
            a = fmaf(W2[k * 128 + c], Wg[c * 16 + w], a);
        __half h = __float2half_rn(a);
        g_Wgphi[j] = h;
        g_Wgplo[j] = __float2half_rn(a - __half2float(h));
    } else if (i < 61456) {
        int w = i - 61440;
        float a = bg[w];
        for (int c = 0; c < 128; ++c)
            a = fmaf(b2[c], Wg[c * 16 + w], a);
        g_bgp[w] = a;
    } else if (i < 77840) {
        int j = i - 61456;
        float val = uW1[j];
        __half h = __float2half_rn(val);
        g_U1ahi[j] = h;
        g_U1alo[j] = __float2half_rn(val - __half2float(h));
    } else if (i < 98320) {
        int j = i - 77840;                       // uW1 rows 128..287
        float val = uW1[128 * 128 + j];
        __half h = __float2half_rn(val);
        g_U1bhi[j] = h;
        g_U1blo[j] = __float2half_rn(val - __half2float(h));
    } else if (i < 114704) {
        int j = i - 98320;
        float val = uW2[j];
        __half h = __float2half_rn(val);
        g_U2hi[j] = h;
        g_U2lo[j] = __float2half_rn(val - __half2float(h));
    } else if (i < 116752) {
        int j = i - 114704;
        int k = j >> 4, w = j & 15;
        float a = 0.0f;
        for (int c = 0; c < 128; ++c)
            a = fmaf(uW2[k * 128 + c], uWg[c * 16 + w], a);
        __half h = __float2half_rn(a);
        g_UWgphi[j] = h;
        g_UWgplo[j] = __float2half_rn(a - __half2float(h));
    } else if (i < 116768) {
        int w = i - 116752;
        float a = ubg[w];
        for (int c = 0; c < 128; ++c)
            a = fmaf(ub2[c], uWg[c * 16 + w], a);
        g_ubgp[w] = a;
    }
}

// ---------------------------------------------------------------------------
// Per-node prep: zeroes aggregation buffers + norms + v-projection partials.
// ---------------------------------------------------------------------------
__global__ __launch_bounds__(256) void prep_nodes(const float* __restrict__ v,
                                                  const float* __restrict__ Wv,
                                                  const float* __restrict__ uWv,
                                                  int n) {
    __shared__ float sv[32 * 48];
    __shared__ float sw[528];
    __shared__ float swu[256];
    const int tid = threadIdx.x;
    const int n0 = blockIdx.x * 32;

    // zero agg buffers for this node range
    for (int q = tid; q < 32 * 32; q += 256) {
        int i = q >> 5, p = q & 31;
        int nd = n0 + i;
        if (nd < n)
            *(float4*)&g_agg_s[(size_t)nd * 128 + p * 4] = make_float4(0, 0, 0, 0);
    }
    for (int q = tid; q < 32 * 12; q += 256) {
        int i = q / 12, p = q - i * 12;
        int nd = n0 + i;
        if (nd < n)
            *(float4*)&g_agg_v[(size_t)nd * 48 + p * 4] = make_float4(0, 0, 0, 0);
    }

    for (int q = tid; q < 32 * 48; q += 256) {
        int i = q / 48, k = q - i * 48;
        int nd = min(n0 + i, n - 1);
        sv[q] = v[(size_t)nd * 48 + k];
    }
    for (int q = tid; q < 528; q += 256) sw[q] = Wv[q];
    for (int q = tid; q < 256; q += 256) swu[q] = uWv[q];
    __syncthreads();

    for (int q = tid; q < 32 * 16; q += 256) {
        int i = q >> 4, j = q & 15;
        if (n0 + i >= n) continue;
        float a = sv[i * 48 + j * 3], b = sv[i * 48 + j * 3 + 1],
              c = sv[i * 48 + j * 3 + 2];
        g_vn[(size_t)(n0 + i) * 16 + j] = sqrtf(fmaxf(a * a + b * b + c * c, 1e-8f));
    }
    for (int q = tid; q < 32 * 48; q += 256) {
        int i = q / 48, r = q - i * 48;
        if (n0 + i >= n) continue;
        int w = r / 3, c = r - w * 3;
        float a = 0.0f, b = 0.0f, u = 0.0f;
#pragma unroll
        for (int j = 0; j < 16; ++j) {
            float vv = sv[i * 48 + j * 3 + c];
            a = fmaf(vv, sw[j * 16 + w], a);
            b = fmaf(vv, sw[(16 + j) * 16 + w], b);
            u = fmaf(vv, swu[j * 16 + w], u);
        }
        g_VA[(size_t)(n0 + i) * 48 + r] = a;
        g_VB[(size_t)(n0 + i) * 48 + r] = b;
        g_UVA[(size_t)(n0 + i) * 48 + r] = u;
    }
}

// ---------------------------------------------------------------------------
// Y kernel: 64-row M tiles. blockIdx.y selects output (Y1/Y2/Z).
// ---------------------------------------------------------------------------
__global__ __launch_bounds__(256) void y_kernel(const float* __restrict__ s, int n) {
    __shared__ __align__(16) char ysm[3072 + 8704];
    const uint32_t smb = smem_to_u32(ysm);
    const int tid = threadIdx.x;
    const int lane = tid & 31;
    const int wid = tid >> 5;
    const int n0 = blockIdx.x * 64;

    const __half* Whi;
    const __half* Wlo;
    float* Y;
    if (blockIdx.y == 0)      { Whi = g_W1ahi; Wlo = g_W1alo; Y = g_Y1; }
    else if (blockIdx.y == 1) { Whi = g_W1bhi; Wlo = g_W1blo; Y = g_Y2; }
    else                      { Whi = g_U1ahi; Wlo = g_U1alo; Y = g_Z; }

    const int mw = (wid & 3) * 16;
    const int nw = (wid >> 2) * 64;
    const int arow = lane & 15;
    const int acol = lane >> 4;
    const int xe = tid >> 2;
    const int xkg = (tid & 3) * 4;

    float acc[8][4];
#pragma unroll
    for (int nt = 0; nt < 8; ++nt)
#pragma unroll
        for (int r = 0; r < 4; ++r) acc[nt][r] = 0.0f;

    for (int kt = 0; kt < 8; ++kt) {
        {
            int nd = min(n0 + xe, n - 1);
            const float* sp = s + (size_t)nd * 128 + kt * 16 + xkg;
            *(uint32_t*)(ysm + xe * 48 + xkg * 2)       = pack_h2(sp[0], sp[1]);
            *(uint32_t*)(ysm + xe * 48 + (xkg + 2) * 2) = pack_h2(sp[2], sp[3]);
        }
        for (int q = tid; q < 2048; q += 256) {
            int kk = q >> 7, nc = q & 127;
            *(__half*)(ysm + 3072 + kk * 272 + nc * 2) = Whi[(kt * 16 + kk) * 128 + nc];
            *(__half*)(ysm + 3072 + 4352 + kk * 272 + nc * 2) = Wlo[(kt * 16 + kk) * 128 + nc];
        }
        __syncthreads();
        uint32_t ah[4];
        ldsm4(smb + (mw + arow) * 48 + acol * 16, ah);
#pragma unroll
        for (int nb = 0; nb < 4; ++nb) {
            uint32_t bh[4], bl[4];
            uint32_t baddr = smb + 3072 + arow * 272 + (nw + nb * 16 + acol * 8) * 2;
            ldsm4t(baddr, bh);
            ldsm4t(baddr + 4352, bl);
            mma_f16(acc[2 * nb],     ah, bh);
            mma_f16(acc[2 * nb + 1], ah, bh + 2);
            mma_f16(acc[2 * nb],     ah, bl);
            mma_f16(acc[2 * nb + 1], ah, bl + 2);
        }
        __syncthreads();
    }
    {
        int r0 = mw + (lane >> 2);
#pragma unroll
        for (int nt = 0; nt < 8; ++nt) {
            int nc = nw + nt * 8 + (lane & 3) * 2;
            if (n0 + r0 < n) {
                float2 u = make_float2(acc[nt][0], acc[nt][1]);
                *(float2*)&Y[(size_t)(n0 + r0) * 128 + nc] = u;
            }
            if (n0 + r0 + 8 < n) {
                float2 u = make_float2(acc[nt][2], acc[nt][3]);
                *(float2*)&Y[(size_t)(n0 + r0 + 8) * 128 + nc] = u;
            }
        }
    }
}

// ===========================================================================
// Edge kernel (r14, verified): 64 edges/CTA, 256 threads, 4 CTAs/SM target.
// ===========================================================================
#define BE 64
#define OB_T     0
#define OB_X     0
#define OB_NORM  6144
#define OB_W     17408
#define OB_WGP   34816
#define OB_WGPLO 38912
#define OB_SG    43008
#define OB_SEV   47104
#define OB_WV32  48128
#define OB_SRC   48192
#define OB_DST   48448
#define EDGE_SMEM_BYTES 48704
#define XBUF(b)  (OB_X + (b) * 3072)
#define WBUF(b)  (OB_W + (b) * 8704)
#define WLO_OFF  4352

__device__ __forceinline__ float fetch_x80(int k, int e, int eg,
    const float* __restrict__ es, const float* snorm)
{
    if (k < 32)   return es[eg * 32 + k];
    if (k == 32)  return snorm[e * 36 + 32];
    if (k < 66)   return snorm[e * 36 + (k - 33)];
    return 0.0f;
}

__global__ __launch_bounds__(256, 4) void edge_kernel(
    const int* __restrict__ ei, const float* __restrict__ es,
    const float* __restrict__ ev,
    const float* __restrict__ b1, const float* __restrict__ b2,
    const float* __restrict__ Wv, int E)
{
    extern __shared__ __align__(16) char smraw[];
    float* smf = (float*)smraw;
    const uint32_t smb = smem_to_u32(smraw);

    const int tid = threadIdx.x;
    const int lane = tid & 31;
    const int wid = tid >> 5;
    const int e0 = blockIdx.x * BE;
    const int nval = min(BE, E - e0);

    int* ssrc = (int*)(smraw + OB_SRC);
    int* sdst = (int*)(smraw + OB_DST);
    float* snorm = (float*)(smraw + OB_NORM);

    if (tid < BE) {
        int ee = e0 + min(tid, nval - 1);
        ssrc[tid] = ei[ee];
        sdst[tid] = ei[E + ee];
    }
    if (tid >= 240) {
        smf[OB_WV32 / 4 + (tid - 240)] = Wv[32 * 16 + (tid - 240)];
    }
    __syncthreads();
    for (int q = tid; q < 512; q += 256) {
        int e = q >> 3, p = q & 7;
        float4 t = (p < 4)
            ? *(const float4*)&g_vn[(size_t)ssrc[e] * 16 + p * 4]
            : *(const float4*)&g_vn[(size_t)sdst[e] * 16 + (p - 4) * 4];
        *(float4*)&snorm[e * 36 + (p < 4 ? p * 4 : 16 + (p - 4) * 4)] = t;
    }
    if (tid < BE) {
        int eg = e0 + min(tid, nval - 1);
        float a = ev[eg * 3], b = ev[eg * 3 + 1], c = ev[eg * 3 + 2];
        float nn = sqrtf(fmaxf(a * a + b * b + c * c, 1e-8f));
        snorm[tid * 36 + 32] = nn;
        float* se = smf + OB_SEV / 4 + tid * 4;
        se[0] = a; se[1] = b; se[2] = c; se[3] = nn;
    }
    __syncthreads();

    const int mw = (wid & 3) * 16;
    const int nw = (wid >> 2) * 64;
    const int arow = lane & 15;
    const int acol = lane >> 4;
    const int xe = tid >> 2;
    const int xkg = (tid & 3) * 4;
    const int wkk = tid >> 4;
    const int wn8 = (tid & 15) * 8;
    const uint32_t wdst_rel = (uint32_t)(wkk * 272 + wn8 * 2);

    float acc[8][4];
    float gacc[2][4];

    {
        const int r0 = mw + (lane >> 2);
        const int r1 = r0 + 8;
        const int cbase = nw + (lane & 3) * 2;
        const float* y1a = g_Y1 + (size_t)ssrc[r0] * 128;
        const float* y2a = g_Y2 + (size_t)sdst[r0] * 128;
        const float* y1b = g_Y1 + (size_t)ssrc[r1] * 128;
        const float* y2b = g_Y2 + (size_t)sdst[r1] * 128;
#pragma unroll
        for (int nt = 0; nt < 8; ++nt) {
            int nc = cbase + nt * 8;
            float2 a = *(const float2*)&y1a[nc];
            float2 b = *(const float2*)&y2a[nc];
            float2 c = *(const float2*)&y1b[nc];
            float2 d = *(const float2*)&y2b[nc];
            acc[nt][0] = a.x + b.x;
            acc[nt][1] = a.y + b.y;
            acc[nt][2] = c.x + d.x;
            acc[nt][3] = c.y + d.y;
        }
    }

    float xr[4];

    {
        cp_async16(smb + WBUF(0) + wdst_rel, &g_W1phi[wkk * 128 + wn8]);
        CP_COMMIT();
        int eg = e0 + min(xe, nval - 1);
#pragma unroll
        for (int u = 0; u < 4; ++u)
            xr[u] = fetch_x80(xkg + u, xe, eg, es, snorm);
        *(uint32_t*)(smraw + XBUF(0) + xe * 48 + xkg * 2)       = pack_h2(xr[0], xr[1]);
        *(uint32_t*)(smraw + XBUF(0) + xe * 48 + (xkg + 2) * 2) = pack_h2(xr[2], xr[3]);
        CP_WAIT0();
    }
    __syncthreads();

    for (int kt = 0; kt < 5; ++kt) {
        const int cur = kt & 1, nxt = cur ^ 1;
        const bool more = (kt + 1 < 5);
        if (more) {
            int kbase = (kt + 1) * 16;
            cp_async16(smb + WBUF(nxt) + wdst_rel, &g_W1phi[(kbase + wkk) * 128 + wn8]);
            CP_COMMIT();
            int eg = e0 + min(xe, nval - 1);
#pragma unroll
            for (int u = 0; u < 4; ++u)
                xr[u] = fetch_x80(kbase + xkg + u, xe, eg, es, snorm);
        }
        {
            uint32_t ah[4];
            ldsm4(smb + XBUF(cur) + (mw + arow) * 48 + acol * 16, ah);
#pragma unroll
            for (int nb = 0; nb < 4; ++nb) {
                uint32_t bh[4];
                uint32_t baddr = smb + WBUF(cur) + arow * 272 + (nw + nb * 16 + acol * 8) * 2;
                ldsm4t(baddr, bh);
                mma_f16(acc[2 * nb],     ah, bh);
                mma_f16(acc[2 * nb + 1], ah, bh + 2);
            }
        }
        if (more) {
            *(uint32_t*)(smraw + XBUF(nxt) + xe * 48 + xkg * 2)       = pack_h2(xr[0], xr[1]);
            *(uint32_t*)(smraw + XBUF(nxt) + xe * 48 + (xkg + 2) * 2) = pack_h2(xr[2], xr[3]);
        }
        CP_WAIT0();
        __syncthreads();
    }

    cp_async16(smb + WBUF(0) + wdst_rel, &g_W2hi[wkk * 128 + wn8]);
    cp_async16(smb + WBUF(0) + WLO_OFF + wdst_rel, &g_W2lo[wkk * 128 + wn8]);
    CP_COMMIT();
    {
        int r0 = mw + (lane >> 2);
#pragma unroll
        for (int nt = 0; nt < 8; ++nt) {
            int n = nw + nt * 8 + (lane & 3) * 2;
            float2 bb = *(const float2*)&b1[n];
            float h0 = acc[nt][0] + bb.x, h1 = acc[nt][1] + bb.y;
            float h2 = acc[nt][2] + bb.x, h3 = acc[nt][3] + bb.y;
            float t0 = h0 * sigmoidf_(h0), t1 = h1 * sigmoidf_(h1);
            float t2 = h2 * sigmoidf_(h2), t3 = h3 * sigmoidf_(h3);
            *(uint32_t*)(smraw + OB_T + r0 * 272 + n * 2)       = pack_h2(t0, t1);
            *(uint32_t*)(smraw + OB_T + (r0 + 8) * 272 + n * 2) = pack_h2(t2, t3);
        }
    }
    for (int q = tid; q < 1024; q += 256) {
        ((uint32_t*)(smraw + OB_WGP))[q]   = ((const uint32_t*)g_Wgphi)[q];
        ((uint32_t*)(smraw + OB_WGPLO))[q] = ((const uint32_t*)g_Wgplo)[q];
    }
    CP_WAIT0();
    __syncthreads();

#pragma unroll
    for (int nt = 0; nt < 8; ++nt)
#pragma unroll
        for (int r = 0; r < 4; ++r) acc[nt][r] = 0.0f;
#pragma unroll
    for (int gn = 0; gn < 2; ++gn)
#pragma unroll
        for (int r = 0; r < 4; ++r) gacc[gn][r] = 0.0f;

    for (int kt = 0; kt < 8; ++kt) {
        const int cur = kt & 1, nxt = cur ^ 1;
        const bool more = (kt + 1 < 8);
        if (more) {
            int kbase = (kt + 1) * 16;
            cp_async16(smb + WBUF(nxt) + wdst_rel, &g_W2hi[(kbase + wkk) * 128 + wn8]);
            cp_async16(smb + WBUF(nxt) + WLO_OFF + wdst_rel, &g_W2lo[(kbase + wkk) * 128 + wn8]);
            CP_COMMIT();
        }
        {
            uint32_t ah[4];
            ldsm4(smb + OB_T + (mw + arow) * 272 + (kt * 16 + acol * 8) * 2, ah);
#pragma unroll
            for (int nb = 0; nb < 4; ++nb) {
                uint32_t bh[4], bl[4];
                uint32_t baddr = smb + WBUF(cur) + arow * 272 + (nw + nb * 16 + acol * 8) * 2;
                ldsm4t(baddr, bh);
                ldsm4t(baddr + WLO_OFF, bl);
                mma_f16(acc[2 * nb],     ah, bh);
                mma_f16(acc[2 * nb + 1], ah, bh + 2);
                mma_f16(acc[2 * nb],     ah, bl);
                mma_f16(acc[2 * nb + 1], ah, bl + 2);
            }
            if (wid < 4) {
                uint32_t gh[4], gl[4];
                uint32_t gaddr = smb + OB_WGP + kt * 512 + arow * 32 + acol * 16;
                ldsm4t(gaddr, gh);
                ldsm4t(gaddr + (OB_WGPLO - OB_WGP), gl);
                mma_f16(gacc[0], ah, gh);
                mma_f16(gacc[1], ah, gh + 2);
                mma_f16(gacc[0], ah, gl);
                mma_f16(gacc[1], ah, gl + 2);
            }
        }
        CP_WAIT0();
        __syncthreads();
    }

    float* sg = smf + OB_SG / 4;
    {
        int r0 = mw + (lane >> 2);
        int r1 = r0 + 8;
        float* d0 = &g_agg_s[(size_t)sdst[r0] * 128];
        float* d1 = &g_agg_s[(size_t)sdst[r1] * 128];
        bool v0 = (r0 < nval), v1 = (r1 < nval);
#pragma unroll
        for (int nt = 0; nt < 8; ++nt) {
            int n = nw + nt * 8 + (lane & 3) * 2;
            float2 bb = *(const float2*)&b2[n];
            if (v0) red2(d0 + n, acc[nt][0] + bb.x, acc[nt][1] + bb.y);
            if (v1) red2(d1 + n, acc[nt][2] + bb.x, acc[nt][3] + bb.y);
        }
        if (wid < 4) {
#pragma unroll
            for (int gn = 0; gn < 2; ++gn) {
                int col = gn * 8 + (lane & 3) * 2;
                float b0 = g_bgp[col], b1g = g_bgp[col + 1];
                sg[r0 * 16 + col]     = sigmoidf_(gacc[gn][0] + b0);
                sg[r0 * 16 + col + 1] = sigmoidf_(gacc[gn][1] + b1g);
                sg[r1 * 16 + col]     = sigmoidf_(gacc[gn][2] + b0);
                sg[r1 * 16 + col + 1] = sigmoidf_(gacc[gn][3] + b1g);
            }
        }
    }
    __syncthreads();

    for (int q = tid; q < BE * 12; q += 256) {
        int e = q / 12, rq = q - e * 12;
        if (e >= nval) continue;
        float4 a4 = *(const float4*)&g_VA[(size_t)ssrc[e] * 48 + rq * 4];
        float4 b4 = *(const float4*)&g_VB[(size_t)sdst[e] * 48 + rq * 4];
        float av[4] = {a4.x + b4.x, a4.y + b4.y, a4.z + b4.z, a4.w + b4.w};
        float out[4];
#pragma unroll
        for (int u = 0; u < 4; ++u) {
            int r = rq * 4 + u, w = r / 3, c3 = r - w * 3;
            float val = av[u] + smf[OB_SEV / 4 + e * 4 + c3] * smf[OB_WV32 / 4 + w];
            out[u] = val * sg[e * 16 + w];
        }
        red4(&g_agg_v[(size_t)sdst[e] * 48 + rq * 4], out[0], out[1], out[2], out[3]);
    }
}

// ===========================================================================
// Node kernel (mma): 64 nodes/CTA, 256 threads.
// A = [agg_s(128) | vn(16) | avn(16)] K=160 fp16; acc init from Z;
// GEMM2 uW2 2-term + fused gate; LN + v_out epilogues.
// smem (64512 B):
//   A @0 [64][176]h stride 352 (22528); T overlays @0 [64][136]h (17408)
//   W dbl @22528 (2x8704) -> 39936 ; UWgp hi @39936, lo @44032 -> 48128
//   vinB f32[64][48] @48128 -> 60416 ; sg/avn f32[64][16] @60416 -> 64512
//   ds overlays @0 f32[64][132] (33792; A/T/Wbuf0 dead)
// ===========================================================================
#define NB 64
#define NB_A     0
#define NB_T     0
#define NB_W     22528
#define NB_WGP   39936
#define NB_WGPLO 44032
#define NB_VIN   48128
#define NB_SG    60416
#define NB_DS    0
#define NODE_SMEM_BYTES 64512
#define NWBUF(b) (NB_W + (b) * 8704)

__global__ __launch_bounds__(256, 2) void node_kernel(
    const float* __restrict__ s, const float* __restrict__ v,
    const float* __restrict__ ub1, const float* __restrict__ ub2,
    const float* __restrict__ uWv,
    const float* __restrict__ lng, const float* __restrict__ lnb,
    float* __restrict__ out_s, float* __restrict__ out_v, int n)
{
    extern __shared__ __align__(16) char smraw[];
    float* smf = (float*)smraw;
    const uint32_t smb = smem_to_u32(smraw);

    const int tid = threadIdx.x;
    const int lane = tid & 31;
    const int wid = tid >> 5;
    const int n0 = blockIdx.x * NB;

    float* vinB = smf + NB_VIN / 4;   // [64][48]
    float* avn  = smf + NB_SG / 4;    // [64][16] (later reused as sg)

    // ---- load agg_v, compute avn ----
    for (int q = tid; q < NB * 12; q += 256) {
        int i = q / 12, p = q - i * 12;
        int nd = min(n0 + i, n - 1);
        *(float4*)&vinB[i * 48 + p * 4] =
            *(const float4*)&g_agg_v[(size_t)nd * 48 + p * 4];
    }
    __syncthreads();
    for (int q = tid; q < NB * 16; q += 256) {
        int i = q >> 4, j = q & 15;
        float a = vinB[i * 48 + j * 3], b = vinB[i * 48 + j * 3 + 1],
              c = vinB[i * 48 + j * 3 + 2];
        avn[i * 16 + j] = sqrtf(fmaxf(a * a + b * b + c * c, 1e-8f));
    }
    __syncthreads();

    const int mw = (wid & 3) * 16;
    const int nw = (wid >> 2) * 64;
    const int arow = lane & 15;
    const int acol = lane >> 4;
    const int wkk = tid >> 4;
    const int wn8 = (tid & 15) * 8;
    const uint32_t wdst_rel = (uint32_t)(wkk * 272 + wn8 * 2);

    // ---- build A fp16 [64][160], stride 352 B; prefetch W tile0 ----
    cp_async16(smb + NWBUF(0) + wdst_rel, &g_U1bhi[wkk * 128 + wn8]);
    cp_async16(smb + NWBUF(0) + WLO_OFF + wdst_rel, &g_U1blo[wkk * 128 + wn8]);
    CP_COMMIT();
    for (int q = tid; q < NB * 80; q += 256) {
        int row = q / 80, kp = q - row * 80;
        int k = kp * 2;
        int nd = min(n0 + row, n - 1);
        float x0, x1;
        if (k < 128) {
            float2 t = *(const float2*)&g_agg_s[(size_t)nd * 128 + k];
            x0 = t.x; x1 = t.y;
        } else if (k < 144) {
            x0 = g_vn[(size_t)nd * 16 + (k - 128)];
            x1 = g_vn[(size_t)nd * 16 + (k - 127)];
        } else {
            x0 = avn[row * 16 + (k - 144)];
            x1 = avn[row * 16 + (k - 143)];
        }
        *(uint32_t*)(smraw + NB_A + row * 352 + k * 2) = pack_h2(x0, x1);
    }
    CP_WAIT0();
    __syncthreads();

    // ---- acc init from Z ----
    float acc[8][4];
    float gacc[2][4];
    {
        int r0 = mw + (lane >> 2);
        int r1 = r0 + 8;
        int nd0 = min(n0 + r0, n - 1);
        int nd1 = min(n0 + r1, n - 1);
        const float* z0 = g_Z + (size_t)nd0 * 128;
        const float* z1 = g_Z + (size_t)nd1 * 128;
        int cbase = nw + (lane & 3) * 2;
#pragma unroll
        for (int nt = 0; nt < 8; ++nt) {
            int nc = cbase + nt * 8;
            float2 a = *(const float2*)&z0[nc];
            float2 b = *(const float2*)&z1[nc];
            acc[nt][0] = a.x; acc[nt][1] = a.y;
            acc[nt][2] = b.x; acc[nt][3] = b.y;
        }
    }

    // ================= GEMM1: K=160 (10 tiles), 2-term W ======================
    for (int kt = 0; kt < 10; ++kt) {
        const int cur = kt & 1, nxt = cur ^ 1;
        const bool more = (kt + 1 < 10);
        if (more) {
            int kbase = (kt + 1) * 16;
            cp_async16(smb + NWBUF(nxt) + wdst_rel, &g_U1bhi[(kbase + wkk) * 128 + wn8]);
            cp_async16(smb + NWBUF(nxt) + WLO_OFF + wdst_rel, &g_U1blo[(kbase + wkk) * 128 + wn8]);
            CP_COMMIT();
        }
        {
            uint32_t ah[4];
            ldsm4(smb + NB_A + (mw + arow) * 352 + (kt * 16 + acol * 8) * 2, ah);
#pragma unroll
            for (int nb = 0; nb < 4; ++nb) {
                uint32_t bh[4], bl[4];
                uint32_t baddr = smb + NWBUF(cur) + arow * 272 + (nw + nb * 16 + acol * 8) * 2;
                ldsm4t(baddr, bh);
                ldsm4t(baddr + WLO_OFF, bl);
                mma_f16(acc[2 * nb],     ah, bh);
                mma_f16(acc[2 * nb + 1], ah, bh + 2);
                mma_f16(acc[2 * nb],     ah, bl);
                mma_f16(acc[2 * nb + 1], ah, bl + 2);
            }
        }
        CP_WAIT0();
        __syncthreads();
    }

    // ---- epilogue 1: +ub1, silu -> T (overlays A); stage UWgp; W2 tile0 ----
    cp_async16(smb + NWBUF(0) + wdst_rel, &g_U2hi[wkk * 128 + wn8]);
    cp_async16(smb + NWBUF(0) + WLO_OFF + wdst_rel, &g_U2lo[wkk * 128 + wn8]);
    CP_COMMIT();
    {
        int r0 = mw + (lane >> 2);
#pragma unroll
        for (int nt = 0; nt < 8; ++nt) {
            int nc = nw + nt * 8 + (lane & 3) * 2;
            float2 bb = *(const float2*)&ub1[nc];
            float h0 = acc[nt][0] + bb.x, h1 = acc[nt][1] + bb.y;
            float h2 = acc[nt][2] + bb.x, h3 = acc[nt][3] + bb.y;
            float t0 = h0 * sigmoidf_(h0), t1 = h1 * sigmoidf_(h1);
            float t2 = h2 * sigmoidf_(h2), t3 = h3 * sigmoidf_(h3);
            *(uint32_t*)(smraw + NB_T + r0 * 272 + nc * 2)       = pack_h2(t0, t1);
            *(uint32_t*)(smraw + NB_T + (r0 + 8) * 272 + nc * 2) = pack_h2(t2, t3);
        }
    }
    for (int q = tid; q < 1024; q += 256) {
        ((uint32_t*)(smraw + NB_WGP))[q]   = ((const uint32_t*)g_UWgphi)[q];
        ((uint32_t*)(smraw + NB_WGPLO))[q] = ((const uint32_t*)g_UWgplo)[q];
    }
    CP_WAIT0();
    __syncthreads();

    // ================= GEMM2: ds = T @ uW2 (K=128, 2-term) + fused gate ======
#pragma unroll
    for (int nt = 0; nt < 8; ++nt)
#pragma unroll
        for (int r = 0; r < 4; ++r) acc[nt][r] = 0.0f;
#pragma unroll
    for (int gn = 0; gn < 2; ++gn)
#pragma unroll
        for (int r = 0; r < 4; ++r) gacc[gn][r] = 0.0f;

    for (int kt = 0; kt < 8; ++kt) {
        const int cur = kt & 1, nxt = cur ^ 1;
        const bool more = (kt + 1 < 8);
        if (more) {
            int kbase = (kt + 1) * 16;
            cp_async16(smb + NWBUF(nxt) + wdst_rel, &g_U2hi[(kbase + wkk) * 128 + wn8]);
            cp_async16(smb + NWBUF(nxt) + WLO_OFF + wdst_rel, &g_U2lo[(kbase + wkk) * 128 + wn8]);
            CP_COMMIT();
        }
        {
            uint32_t ah[4];
            ldsm4(smb + NB_T + (mw + arow) * 272 + (kt * 16 + acol * 8) * 2, ah);
#pragma unroll
            for (int nb = 0; nb < 4; ++nb) {
                uint32_t bh[4], bl[4];
                uint32_t baddr = smb + NWBUF(cur) + arow * 272 + (nw + nb * 16 + acol * 8) * 2;
                ldsm4t(baddr, bh);
                ldsm4t(baddr + WLO_OFF, bl);
                mma_f16(acc[2 * nb],     ah, bh);
                mma_f16(acc[2 * nb + 1], ah, bh + 2);
                mma_f16(acc[2 * nb],     ah, bl);
                mma_f16(acc[2 * nb + 1], ah, bl + 2);
            }
            if (wid < 4) {
                uint32_t gh[4], gl[4];
                uint32_t gaddr = smb + NB_WGP + kt * 512 + arow * 32 + acol * 16;
                ldsm4t(gaddr, gh);
                ldsm4t(gaddr + (NB_WGPLO - NB_WGP), gl);
                mma_f16(gacc[0], ah, gh);
                mma_f16(gacc[1], ah, gh + 2);
                mma_f16(gacc[0], ah, gl);
                mma_f16(gacc[1], ah, gl + 2);
            }
        }
        CP_WAIT0();
        __syncthreads();
    }

    // ---- epilogue 2: ds -> smem (+ub2); gates -> sg (overwrites avn) ----
    float* ds = smf + NB_DS / 4;   // [64][132]
    float* sg = smf + NB_SG / 4;   // [64][16]
    {
        int r0 = mw + (lane >> 2);
#pragma unroll
        for (int nt = 0; nt < 8; ++nt) {
            int nc = nw + nt * 8 + (lane & 3) * 2;
            float2 bb = *(const float2*)&ub2[nc];
            ds[r0 * 132 + nc]           = acc[nt][0] + bb.x;
            ds[r0 * 132 + nc + 1]       = acc[nt][1] + bb.y;
            ds[(r0 + 8) * 132 + nc]     = acc[nt][2] + bb.x;
            ds[(r0 + 8) * 132 + nc + 1] = acc[nt][3] + bb.y;
        }
        if (wid < 4) {
#pragma unroll
            for (int gn = 0; gn < 2; ++gn) {
                int col = gn * 8 + (lane & 3) * 2;
                float b0 = g_ubgp[col], b1g = g_ubgp[col + 1];
                sg[r0 * 16 + col]           = sigmoidf_(gacc[gn][0] + b0);
                sg[r0 * 16 + col + 1]       = sigmoidf_(gacc[gn][1] + b1g);
                sg[(r0 + 8) * 16 + col]     = sigmoidf_(gacc[gn][2] + b0);
                sg[(r0 + 8) * 16 + col + 1] = sigmoidf_(gacc[gn][3] + b1g);
            }
        }
    }
    __syncthreads();

    // ---- LayerNorm: 4 threads per row, 32 cols each ----
    {
        int row = tid >> 2, c4 = tid & 3;
        int nd = n0 + row;
        bool valid = (nd < n);
        int ndc = min(nd, n - 1);
        const float* sp = s + (size_t)ndc * 128 + c4 * 32;
        const float* dp = ds + row * 132 + c4 * 32;
        float sum = 0.0f, sq = 0.0f;
#pragma unroll 8
        for (int j = 0; j < 32; ++j) {
            float x = sp[j] + dp[j];
            sum += x; sq = fmaf(x, x, sq);
        }
        sum += __shfl_xor_sync(0xffffffffu, sum, 1);
        sq  += __shfl_xor_sync(0xffffffffu, sq,  1);
        sum += __shfl_xor_sync(0xffffffffu, sum, 2);
        sq  += __shfl_xor_sync(0xffffffffu, sq,  2);
        float mu = sum * (1.0f / 128.0f);
        float var = sq * (1.0f / 128.0f) - mu * mu;
        float rstd = rsqrtf(var + 1e-5f);
        if (valid) {
            float* op = out_s + (size_t)nd * 128 + c4 * 32;
            const float* gp = lng + c4 * 32;
            const float* bp = lnb + c4 * 32;
#pragma unroll 8
            for (int j = 0; j < 32; ++j) {
                float x = sp[j] + dp[j];
                op[j] = (x - mu) * rstd * gp[j] + bp[j];
            }
        }
    }

    // ---- v_out ----
    for (int q = tid; q < NB * 12; q += 256) {
        int i = q / 12, rq = q - i * 12;
        int nd = n0 + i;
        if (nd >= n) continue;
        float out[4];
#pragma unroll
        for (int u = 0; u < 4; ++u) {
            int r = rq * 4 + u, w = r / 3, c3 = r - w * 3;
            float a = g_UVA[(size_t)nd * 48 + r];
#pragma unroll
            for (int j = 0; j < 16; ++j)
                a = fmaf(vinB[i * 48 + j * 3 + c3], uWv[(16 + j) * 16 + w], a);
            out[u] = v[(size_t)nd * 48 + r] + a * sg[i * 16 + w];
        }
        *(float4*)&out_v[(size_t)nd * 48 + rq * 4] =
            make_float4(out[0], out[1], out[2], out[3]);
    }
}

// ---------------------------------------------------------------------------
extern "C" void kernel_launch(void* const* d_in, const int* in_sizes, int n_in,
                              void* d_out, int out_size)
{
    const float* s   = (const float*)d_in[0];
    const float* v   = (const float*)d_in[1];
    const int*   ei  = (const int*)  d_in[2];
    const float* es  = (const float*)d_in[3];
    const float* ev  = (const float*)d_in[4];
    const float* mW1 = (const float*)d_in[5];
    const float* mb1 = (const float*)d_in[6];
    const float* mW2 = (const float*)d_in[7];
    const float* mb2 = (const float*)d_in[8];
    const float* mWv = (const float*)d_in[9];
    const float* mWg = (const float*)d_in[10];
    const float* mbg = (const float*)d_in[11];
    const float* uW1 = (const float*)d_in[12];
    const float* ub1 = (const float*)d_in[13];
    const float* uW2 = (const float*)d_in[14];
    const float* ub2 = (const float*)d_in[15];
    const float* uWv = (const float*)d_in[16];
    const float* uWg = (const float*)d_in[17];
    const float* ubg = (const float*)d_in[18];
    const float* lng = (const float*)d_in[19];
    const float* lnb = (const float*)d_in[20];

    const int n = in_sizes[0] / 128;
    const int E = in_sizes[2] / 2;

    float* out_s = (float*)d_out;
    float* out_v = out_s + (size_t)n * 128;

    cudaFuncSetAttribute(edge_kernel,
                         cudaFuncAttributeMaxDynamicSharedMemorySize,
                         EDGE_SMEM_BYTES);
    cudaFuncSetAttribute(node_kernel,
                         cudaFuncAttributeMaxDynamicSharedMemorySize,
                         NODE_SMEM_BYTES);

    prep_weights<<<(116768 + 255) / 256, 256>>>(mW1, mW2, mb2, mWg, mbg,
                                                uW1, uW2, ub2, uWg, ubg);
    prep_nodes<<<(n + 31) / 32, 256>>>(v, mWv, uWv, n);
    y_kernel<<<dim3((n + 63) / 64, 3), 256>>>(s, n);

    edge_kernel<<<(E + BE - 1) / BE, 256, EDGE_SMEM_BYTES>>>(
        ei, es, ev, mb1, mb2, mWv, E);

    node_kernel<<<(n + NB - 1) / NB, 256, NODE_SMEM_BYTES>>>(
        s, v, ub1, ub2, uWv, lng, lnb, out_s, out_v, n);
}